// round 5
// baseline (speedup 1.0000x reference)
#include <cuda_runtime.h>
#include <cuda_bf16.h>
#include <cstdint>
#include <cstddef>

#define BS 64
#define MU 64
#define KA 64
#define DD 128
#define HH 128

#define ROWP 136                 // padded bf16 elems per smem row (272 B)
#define TILE_R 128               // rows per k3 tile
#define N_TILES 2048             // 262144 / 128
#define K3_THREADS 256
#define K3_GRID 148

// Scratch (device globals: allocation-free per harness rules)
__device__ float g_msgm_part[8][BS * MU * DD];   // 16 MB
__device__ float g_msgk_part[8][BS * KA * DD];   // 16 MB
__device__ float g_zm[BS * MU * HH];             // 2 MB
__device__ float g_zk[BS * KA * HH];             // 2 MB
__device__ __align__(16) __nv_bfloat16 g_xbf16[(size_t)BS * MU * KA * DD];  // 64 MB

__device__ __forceinline__ uint32_t smem_u32(const void* p) {
    uint32_t a;
    asm("{ .reg .u64 t; cvta.to.shared.u64 t, %1; cvt.u32.u64 %0, t; }" : "=r"(a) : "l"(p));
    return a;
}

#define LDSM_X4(r0, r1, r2, r3, addr) \
    asm volatile("ldmatrix.sync.aligned.m8n8.x4.shared.b16 {%0,%1,%2,%3}, [%4];" \
                 : "=r"(r0), "=r"(r1), "=r"(r2), "=r"(r3) : "r"(addr))

#define CP_ASYNC16(dst, src) \
    asm volatile("cp.async.cg.shared.global [%0], [%1], 16;" :: "r"(dst), "l"(src))
#define CP_COMMIT() asm volatile("cp.async.commit_group;" ::: "memory")
#define CP_WAIT2()  asm volatile("cp.async.wait_group 2;" ::: "memory")

// ===========================================================================
// K1: grid = 64b x 8mc x 4kc = 2048 blocks, 128 threads.
// Thread (tp = t>>6, td = t&63) reads float2 at d=2*td on rows with k-parity
// tp. Register accumulation; also emits the bf16 copy of x for k3.
// ===========================================================================
__global__ void __launch_bounds__(128) k1_reduce(const float* __restrict__ in) {
    int bid = blockIdx.x;
    int b = bid >> 5;
    int mc = (bid >> 2) & 7;
    int kc = bid & 3;
    int t = threadIdx.x;
    int tp = t >> 6, td = t & 63;

    // base row = (b*64 + mc*8)*64 + kc*16 + tp ; float2 row stride = 64
    size_t row_base = (size_t)((b * MU + mc * 8) * KA + kc * 16 + tp);
    const float2* in2 = reinterpret_cast<const float2*>(in);
    const float2* base = in2 + row_base * 64 + td;

    float2 ak[8];
#pragma unroll
    for (int j = 0; j < 8; j++) { ak[j].x = 0.f; ak[j].y = 0.f; }

#pragma unroll 1
    for (int m = 0; m < 8; m++) {
        const float2* pm = base + (size_t)m * KA * 64;   // +64 rows
        float2 v[8];
#pragma unroll
        for (int j = 0; j < 8; j++) v[j] = pm[j * 128];  // +2 rows per j
        float2 am; am.x = 0.f; am.y = 0.f;
#pragma unroll
        for (int j = 0; j < 8; j++) {
            am.x += v[j].x; am.y += v[j].y;
            ak[j].x += v[j].x; ak[j].y += v[j].y;
        }
        // msg_m partial (parity tp, chunk kc): slot kc*2+tp
        reinterpret_cast<float2*>(g_msgm_part[kc * 2 + tp])
            [(size_t)(b * MU + mc * 8 + m) * 64 + td] = am;
        // bf16 copy of the 8 rows just read
        size_t mrow = row_base + (size_t)m * KA;
#pragma unroll
        for (int j = 0; j < 8; j++) {
            __nv_bfloat162 p = __floats2bfloat162_rn(v[j].x, v[j].y);
            reinterpret_cast<uint32_t*>(g_xbf16)[(mrow + j * 2) * 64 + td] =
                *reinterpret_cast<uint32_t*>(&p);
        }
    }
#pragma unroll
    for (int j = 0; j < 8; j++)
        reinterpret_cast<float2*>(g_msgk_part[mc])
            [(size_t)(b * KA + kc * 16 + 2 * j + tp) * 64 + td] = ak[j];
}

// ===========================================================================
// K2: zm = msg_m @ Wm^T ; zk = msg_k @ Wk^T  (exact fp32, 8x8 reg tiles)
// ===========================================================================
__global__ void __launch_bounds__(128) k2_bias(const float* __restrict__ Wm,
                                               const float* __restrict__ Wk) {
    extern __shared__ float s2[];
    float* Ws = s2;               // [128][129]
    float* Ms = s2 + 128 * 129;   // [64][129]
    int side = blockIdx.x >> 6;
    int b = blockIdx.x & 63;
    int t = threadIdx.x;

    const float* W = side ? Wk : Wm;
#pragma unroll 4
    for (int i = 0; i < HH; i++) Ws[i * 129 + t] = W[i * DD + t];

#pragma unroll 2
    for (int r = 0; r < 64; r++) {
        float s = 0.f;
        if (!side) {
#pragma unroll
            for (int p = 0; p < 8; p++) s += g_msgm_part[p][(size_t)(b * 64 + r) * DD + t];
        } else {
#pragma unroll
            for (int p = 0; p < 8; p++) s += g_msgk_part[p][(size_t)(b * 64 + r) * DD + t];
        }
        Ms[r * 129 + t] = s;
    }
    __syncthreads();

    int rt = t >> 4;
    int ht = t & 15;
    float acc[8][8];
#pragma unroll
    for (int i = 0; i < 8; i++)
#pragma unroll
        for (int j = 0; j < 8; j++) acc[i][j] = 0.f;

    for (int dd = 0; dd < DD; dd++) {
        float xv[8], wv[8];
#pragma unroll
        for (int i = 0; i < 8; i++) xv[i] = Ms[(rt * 8 + i) * 129 + dd];
#pragma unroll
        for (int j = 0; j < 8; j++) wv[j] = Ws[(ht + 16 * j) * 129 + dd];
#pragma unroll
        for (int i = 0; i < 8; i++)
#pragma unroll
            for (int j = 0; j < 8; j++) acc[i][j] += xv[i] * wv[j];
    }

    float* outp = side ? g_zk : g_zm;
#pragma unroll
    for (int i = 0; i < 8; i++)
#pragma unroll
        for (int j = 0; j < 8; j++)
            outp[(size_t)(b * 64 + rt * 8 + i) * HH + ht + 16 * j] = acc[i][j];
}

// ===========================================================================
// K3: persistent bf16 mma.sync GEMM, cp.async 4-stage A pipeline, fused bias.
// Grid 148 x 256 threads. A tiles (bf16, pre-converted by k1) stream via
// LDGSTS — no register staging, no load stall. B (Wself) converted once.
// SMEM: B [128][136] + 4 x A [128][136] bf16 = 174080 B (1 CTA/SM).
// ===========================================================================
#define K3_SMEM (5 * 34816)

__global__ void __launch_bounds__(K3_THREADS, 1) k3_main(const float* __restrict__ Wself,
                                                         float* __restrict__ out) {
    extern __shared__ __nv_bfloat16 smem[];
    __nv_bfloat16* Bs = smem;                       // [128][136]
    __nv_bfloat16* Abuf = smem + 128 * ROWP;        // 4 x [128][136]

    int t = threadIdx.x;
    int wid = t >> 5, lane = t & 31;
    int lr = lane >> 2, lc = lane & 3;
    int r0 = wid * 16;

    uint32_t sA = smem_u32(Abuf);
    // per-thread cp.async chunk coords: 8 chunks of 16 B, i = t + j*256
    // r = i>>4, c = i&15 ; smem off = r*272 + c*16 ; gmem off = r*256 + c*16

    // ---- prologue: issue 3 stages, then convert B ----
#pragma unroll
    for (int s = 0; s < 3; s++) {
        int tile = blockIdx.x + s * K3_GRID;
        if (tile < N_TILES) {
            const char* src = reinterpret_cast<const char*>(g_xbf16) + (size_t)tile * 32768;
            uint32_t dst = sA + s * 34816;
#pragma unroll
            for (int j = 0; j < 8; j++) {
                int i = t + j * 256;
                int r = i >> 4, c = i & 15;
                CP_ASYNC16(dst + r * 272 + c * 16, src + r * 256 + c * 16);
            }
        }
        CP_COMMIT();
    }
    {   // B: f32 -> bf16, one-time
        const float4* s4 = reinterpret_cast<const float4*>(Wself);
        for (int i = t; i < 128 * 32; i += K3_THREADS) {
            int r = i >> 5, c4 = i & 31;
            float4 v = s4[i];
            __nv_bfloat162 p0 = __floats2bfloat162_rn(v.x, v.y);
            __nv_bfloat162 p1 = __floats2bfloat162_rn(v.z, v.w);
            uint2 u;
            u.x = *reinterpret_cast<uint32_t*>(&p0);
            u.y = *reinterpret_cast<uint32_t*>(&p1);
            *reinterpret_cast<uint2*>(Bs + r * ROWP + c4 * 4) = u;
        }
    }

    // ldmatrix per-lane addresses
    uint32_t a_off = (uint32_t)((r0 + (lane & 7) + ((lane & 8) ? 8 : 0)) * 272 +
                                ((lane & 16) ? 16 : 0));
    uint32_t b_addr0 = smem_u32(Bs) +
                       (uint32_t)((((lane & 16) ? 8 : 0) + (lane & 7)) * 272 +
                                  ((lane & 8) ? 16 : 0));

    int it = 0;
    for (int tile = blockIdx.x; tile < N_TILES; tile += K3_GRID, it++) {
        CP_WAIT2();                 // own group 'it' complete
        __syncthreads();            // cross-thread visibility + reuse safety

        // issue stage it+3
        {
            int t3 = tile + 3 * K3_GRID;
            if (t3 < N_TILES) {
                const char* src = reinterpret_cast<const char*>(g_xbf16) + (size_t)t3 * 32768;
                uint32_t dst = sA + ((it + 3) & 3) * 34816;
#pragma unroll
                for (int j = 0; j < 8; j++) {
                    int i = t + j * 256;
                    int r = i >> 4, c = i & 15;
                    CP_ASYNC16(dst + r * 272 + c * 16, src + r * 256 + c * 16);
                }
            }
            CP_COMMIT();
        }

        // ---- MMA: rows [r0, r0+16) x 128 cols, K = 128 ----
        uint32_t a_cur = sA + (it & 3) * 34816 + a_off;
        float acc[16][4];
#pragma unroll
        for (int nt = 0; nt < 16; nt++)
#pragma unroll
            for (int q = 0; q < 4; q++) acc[nt][q] = 0.f;

#pragma unroll
        for (int kk = 0; kk < 8; kk++) {
            uint32_t a0, a1, a2, a3;
            LDSM_X4(a0, a1, a2, a3, a_cur + kk * 32);
#pragma unroll
            for (int np = 0; np < 8; np++) {
                uint32_t b0, b1, b2, b3;
                LDSM_X4(b0, b1, b2, b3, b_addr0 + np * 16 * 272 + kk * 32);
                asm volatile(
                    "mma.sync.aligned.m16n8k16.row.col.f32.bf16.bf16.f32 "
                    "{%0,%1,%2,%3},{%4,%5,%6,%7},{%8,%9},{%0,%1,%2,%3};"
                    : "+f"(acc[2 * np][0]), "+f"(acc[2 * np][1]),
                      "+f"(acc[2 * np][2]), "+f"(acc[2 * np][3])
                    : "r"(a0), "r"(a1), "r"(a2), "r"(a3), "r"(b0), "r"(b1));
                asm volatile(
                    "mma.sync.aligned.m16n8k16.row.col.f32.bf16.bf16.f32 "
                    "{%0,%1,%2,%3},{%4,%5,%6,%7},{%8,%9},{%0,%1,%2,%3};"
                    : "+f"(acc[2 * np + 1][0]), "+f"(acc[2 * np + 1][1]),
                      "+f"(acc[2 * np + 1][2]), "+f"(acc[2 * np + 1][3])
                    : "r"(a0), "r"(a1), "r"(a2), "r"(a3), "r"(b2), "r"(b3));
            }
        }

        // ---- Epilogue: + zm[bm,:] + zk[bk,:], direct STG.64 ----
        int grow = tile * TILE_R + r0 + lr;
        int bm = grow >> 6;
        int bk = ((grow >> 12) << 6) | (grow & 63);
        const float2* zmrow = reinterpret_cast<const float2*>(g_zm + (size_t)bm * HH);
        const float2* zkr0 = reinterpret_cast<const float2*>(g_zk + (size_t)bk * HH);
        const float2* zkr8 = reinterpret_cast<const float2*>(g_zk + (size_t)(bk + 8) * HH);
        float2* o0 = reinterpret_cast<float2*>(out + (size_t)grow * HH);
        float2* o8 = reinterpret_cast<float2*>(out + (size_t)(grow + 8) * HH);

#pragma unroll
        for (int nt = 0; nt < 16; nt++) {
            int cw = nt * 4 + lc;
            float2 zm2 = zmrow[cw];
            float2 za = zkr0[cw];
            float2 zb = zkr8[cw];
            float2 v0, v8;
            v0.x = acc[nt][0] + zm2.x + za.x;
            v0.y = acc[nt][1] + zm2.y + za.y;
            v8.x = acc[nt][2] + zm2.x + zb.x;
            v8.y = acc[nt][3] + zm2.y + zb.y;
            o0[cw] = v0;
            o8[cw] = v8;
        }
    }
}

// ===========================================================================
extern "C" void kernel_launch(void* const* d_in, const int* in_sizes, int n_in,
                              void* d_out, int out_size) {
    const float* inputs = (const float*)d_in[0];
    const float* Wself  = (const float*)d_in[1];
    const float* Wm     = (const float*)d_in[2];
    const float* Wk     = (const float*)d_in[3];
    float* out = (float*)d_out;
    (void)in_sizes; (void)n_in; (void)out_size;

    const size_t S2 = (size_t)(128 * 129 + 64 * 129) * sizeof(float);
    cudaFuncSetAttribute(k2_bias, cudaFuncAttributeMaxDynamicSharedMemorySize, (int)S2);
    cudaFuncSetAttribute(k3_main, cudaFuncAttributeMaxDynamicSharedMemorySize, K3_SMEM);

    k1_reduce<<<2048, 128>>>(inputs);
    k2_bias<<<128, 128, S2>>>(Wm, Wk);
    k3_main<<<K3_GRID, K3_THREADS, K3_SMEM>>>(Wself, out);
}

// round 6
// speedup vs baseline: 1.0532x; 1.0532x over previous
#include <cuda_runtime.h>
#include <cuda_bf16.h>
#include <cstdint>
#include <cstddef>

#define BS 64
#define MU 64
#define KA 64
#define DD 128
#define HH 128

#define ROWP 136                 // padded bf16 elems per smem row (272 B)
#define TILE_R 64                // rows per k3 tile
#define N_TILES 4096             // 262144 / 64
#define K3_THREADS 256
#define K3_GRID 444              // 3 CTAs/SM x 148
#define A_BUF_B 17408            // 64 rows * 272 B

// Scratch (device globals: allocation-free per harness rules)
__device__ float g_msgm_part[8][BS * MU * DD];   // 16 MB
__device__ float g_msgk_part[8][BS * KA * DD];   // 16 MB
__device__ float g_zm[BS * MU * HH];             // 2 MB
__device__ float g_zk[BS * KA * HH];             // 2 MB
__device__ __align__(16) __nv_bfloat16 g_xbf16[(size_t)BS * MU * KA * DD];  // 64 MB

__device__ __forceinline__ uint32_t smem_u32(const void* p) {
    uint32_t a;
    asm("{ .reg .u64 t; cvta.to.shared.u64 t, %1; cvt.u32.u64 %0, t; }" : "=r"(a) : "l"(p));
    return a;
}

#define LDSM_X4(r0, r1, r2, r3, addr) \
    asm volatile("ldmatrix.sync.aligned.m8n8.x4.shared.b16 {%0,%1,%2,%3}, [%4];" \
                 : "=r"(r0), "=r"(r1), "=r"(r2), "=r"(r3) : "r"(addr))

#define CP_ASYNC16(dst, src) \
    asm volatile("cp.async.cg.shared.global [%0], [%1], 16;" :: "r"(dst), "l"(src))
#define CP_COMMIT() asm volatile("cp.async.commit_group;" ::: "memory")
#define CP_WAIT1()  asm volatile("cp.async.wait_group 1;" ::: "memory")

// ===========================================================================
// K1: grid = 64b x 8mc x 4kc = 2048 blocks, 128 threads.
// Register accumulation; also emits the bf16 copy of x for k3's cp.async.
// ===========================================================================
__global__ void __launch_bounds__(128) k1_reduce(const float* __restrict__ in) {
    int bid = blockIdx.x;
    int b = bid >> 5;
    int mc = (bid >> 2) & 7;
    int kc = bid & 3;
    int t = threadIdx.x;
    int tp = t >> 6, td = t & 63;

    size_t row_base = (size_t)((b * MU + mc * 8) * KA + kc * 16 + tp);
    const float2* in2 = reinterpret_cast<const float2*>(in);
    const float2* base = in2 + row_base * 64 + td;

    float2 ak[8];
#pragma unroll
    for (int j = 0; j < 8; j++) { ak[j].x = 0.f; ak[j].y = 0.f; }

#pragma unroll 1
    for (int m = 0; m < 8; m++) {
        const float2* pm = base + (size_t)m * KA * 64;
        float2 v[8];
#pragma unroll
        for (int j = 0; j < 8; j++) v[j] = pm[j * 128];
        float2 am; am.x = 0.f; am.y = 0.f;
#pragma unroll
        for (int j = 0; j < 8; j++) {
            am.x += v[j].x; am.y += v[j].y;
            ak[j].x += v[j].x; ak[j].y += v[j].y;
        }
        reinterpret_cast<float2*>(g_msgm_part[kc * 2 + tp])
            [(size_t)(b * MU + mc * 8 + m) * 64 + td] = am;
        size_t mrow = row_base + (size_t)m * KA;
#pragma unroll
        for (int j = 0; j < 8; j++) {
            __nv_bfloat162 p = __floats2bfloat162_rn(v[j].x, v[j].y);
            reinterpret_cast<uint32_t*>(g_xbf16)[(mrow + j * 2) * 64 + td] =
                *reinterpret_cast<uint32_t*>(&p);
        }
    }
#pragma unroll
    for (int j = 0; j < 8; j++)
        reinterpret_cast<float2*>(g_msgk_part[mc])
            [(size_t)(b * KA + kc * 16 + 2 * j + tp) * 64 + td] = ak[j];
}

// ===========================================================================
// K2: zm = msg_m @ Wm^T ; zk = msg_k @ Wk^T  (exact fp32, 8x8 reg tiles)
// ===========================================================================
__global__ void __launch_bounds__(128) k2_bias(const float* __restrict__ Wm,
                                               const float* __restrict__ Wk) {
    extern __shared__ float s2[];
    float* Ws = s2;               // [128][129]
    float* Ms = s2 + 128 * 129;   // [64][129]
    int side = blockIdx.x >> 6;
    int b = blockIdx.x & 63;
    int t = threadIdx.x;

    const float* W = side ? Wk : Wm;
#pragma unroll 4
    for (int i = 0; i < HH; i++) Ws[i * 129 + t] = W[i * DD + t];

#pragma unroll 2
    for (int r = 0; r < 64; r++) {
        float s = 0.f;
        if (!side) {
#pragma unroll
            for (int p = 0; p < 8; p++) s += g_msgm_part[p][(size_t)(b * 64 + r) * DD + t];
        } else {
#pragma unroll
            for (int p = 0; p < 8; p++) s += g_msgk_part[p][(size_t)(b * 64 + r) * DD + t];
        }
        Ms[r * 129 + t] = s;
    }
    __syncthreads();

    int rt = t >> 4;
    int ht = t & 15;
    float acc[8][8];
#pragma unroll
    for (int i = 0; i < 8; i++)
#pragma unroll
        for (int j = 0; j < 8; j++) acc[i][j] = 0.f;

    for (int dd = 0; dd < DD; dd++) {
        float xv[8], wv[8];
#pragma unroll
        for (int i = 0; i < 8; i++) xv[i] = Ms[(rt * 8 + i) * 129 + dd];
#pragma unroll
        for (int j = 0; j < 8; j++) wv[j] = Ws[(ht + 16 * j) * 129 + dd];
#pragma unroll
        for (int i = 0; i < 8; i++)
#pragma unroll
            for (int j = 0; j < 8; j++) acc[i][j] += xv[i] * wv[j];
    }

    float* outp = side ? g_zk : g_zm;
#pragma unroll
    for (int i = 0; i < 8; i++)
#pragma unroll
        for (int j = 0; j < 8; j++)
            outp[(size_t)(b * 64 + rt * 8 + i) * HH + ht + 16 * j] = acc[i][j];
}

// ===========================================================================
// K3: persistent bf16 mma.sync GEMM, 3 CTAs/SM for latency hiding.
// Grid 444 x 256 threads (8 warps = 4 row-strips x 2 col-halves).
// Tile = 64 rows; warp = 16 rows x 64 cols (acc 32 regs).
// A (bf16 pre-converted) via cp.async, depth-2 double buffer.
// SMEM/CTA: B [128][136] 34816 + 2 x A [64][136] 17408 = 69632 B.
// ===========================================================================
#define K3_SMEM (34816 + 2 * A_BUF_B)

__global__ void __launch_bounds__(K3_THREADS, 3) k3_main(const float* __restrict__ Wself,
                                                         float* __restrict__ out) {
    extern __shared__ __nv_bfloat16 smem[];
    __nv_bfloat16* Bs = smem;                       // [128][136]
    uint32_t sA = smem_u32(smem + 128 * ROWP);      // 2 x [64][136]

    int t = threadIdx.x;
    int wid = t >> 5, lane = t & 31;
    int lr = lane >> 2, lc = lane & 3;
    int strip = wid & 3;                            // rows strip*16
    int half = wid >> 2;                            // cols half*64
    int r0 = strip * 16;

    // ---- prologue: issue 2 A stages, then convert B ----
#pragma unroll
    for (int s = 0; s < 2; s++) {
        int tile = blockIdx.x + s * K3_GRID;
        if (tile < N_TILES) {
            const char* src = reinterpret_cast<const char*>(g_xbf16) + (size_t)tile * (TILE_R * 256);
            uint32_t dst = sA + s * A_BUF_B;
#pragma unroll
            for (int j = 0; j < 4; j++) {           // 1024 chunks / 256 thr
                int i = t + j * 256;
                int r = i >> 4, c = i & 15;
                CP_ASYNC16(dst + r * 272 + c * 16, src + r * 256 + c * 16);
            }
        }
        CP_COMMIT();
    }
    {   // B: f32 -> bf16, one-time
        const float4* s4 = reinterpret_cast<const float4*>(Wself);
        for (int i = t; i < 128 * 32; i += K3_THREADS) {
            int r = i >> 5, c4 = i & 31;
            float4 v = s4[i];
            __nv_bfloat162 p0 = __floats2bfloat162_rn(v.x, v.y);
            __nv_bfloat162 p1 = __floats2bfloat162_rn(v.z, v.w);
            uint2 u;
            u.x = *reinterpret_cast<uint32_t*>(&p0);
            u.y = *reinterpret_cast<uint32_t*>(&p1);
            *reinterpret_cast<uint2*>(Bs + r * ROWP + c4 * 4) = u;
        }
    }
    __syncthreads();

    // ldmatrix per-lane addresses
    uint32_t a_off = (uint32_t)((r0 + (lane & 7) + ((lane & 8) ? 8 : 0)) * 272 +
                                ((lane & 16) ? 16 : 0));
    uint32_t b_addr0 = smem_u32(Bs) +
                       (uint32_t)((half * 64 + (lane & 7) + ((lane & 16) ? 8 : 0)) * 272 +
                                  ((lane & 8) ? 16 : 0));

    int it = 0;
    for (int tile = blockIdx.x; tile < N_TILES; tile += K3_GRID, it++) {
        CP_WAIT1();                 // group 'it' complete (<=1 pending)
        __syncthreads();

        // ---- MMA: rows [r0, r0+16) x cols [half*64, half*64+64), K = 128 ----
        uint32_t a_cur = sA + (it & 1) * A_BUF_B + a_off;
        float acc[8][4];
#pragma unroll
        for (int nt = 0; nt < 8; nt++)
#pragma unroll
            for (int q = 0; q < 4; q++) acc[nt][q] = 0.f;

#pragma unroll
        for (int kk = 0; kk < 8; kk++) {
            uint32_t a0, a1, a2, a3;
            LDSM_X4(a0, a1, a2, a3, a_cur + kk * 32);
#pragma unroll
            for (int np = 0; np < 4; np++) {
                uint32_t b0, b1, b2, b3;
                LDSM_X4(b0, b1, b2, b3, b_addr0 + np * 16 * 272 + kk * 32);
                asm volatile(
                    "mma.sync.aligned.m16n8k16.row.col.f32.bf16.bf16.f32 "
                    "{%0,%1,%2,%3},{%4,%5,%6,%7},{%8,%9},{%0,%1,%2,%3};"
                    : "+f"(acc[2 * np][0]), "+f"(acc[2 * np][1]),
                      "+f"(acc[2 * np][2]), "+f"(acc[2 * np][3])
                    : "r"(a0), "r"(a1), "r"(a2), "r"(a3), "r"(b0), "r"(b1));
                asm volatile(
                    "mma.sync.aligned.m16n8k16.row.col.f32.bf16.bf16.f32 "
                    "{%0,%1,%2,%3},{%4,%5,%6,%7},{%8,%9},{%0,%1,%2,%3};"
                    : "+f"(acc[2 * np + 1][0]), "+f"(acc[2 * np + 1][1]),
                      "+f"(acc[2 * np + 1][2]), "+f"(acc[2 * np + 1][3])
                    : "r"(a0), "r"(a1), "r"(a2), "r"(a3), "r"(b2), "r"(b3));
            }
        }

        // ---- Epilogue: + zm[bm,:] + zk[bk,:], direct STG.64 ----
        int grow = tile * TILE_R + r0 + lr;
        int bm = grow >> 6;
        int bk = ((grow >> 12) << 6) | (grow & 63);
        const float2* zmrow = reinterpret_cast<const float2*>(g_zm + (size_t)bm * HH);
        const float2* zkr0 = reinterpret_cast<const float2*>(g_zk + (size_t)bk * HH);
        const float2* zkr8 = reinterpret_cast<const float2*>(g_zk + (size_t)(bk + 8) * HH);
        float2* o0 = reinterpret_cast<float2*>(out + (size_t)grow * HH);
        float2* o8 = reinterpret_cast<float2*>(out + (size_t)(grow + 8) * HH);

#pragma unroll
        for (int nt = 0; nt < 8; nt++) {
            int cw = half * 32 + nt * 4 + lc;       // float2 column index
            float2 zm2 = zmrow[cw];
            float2 za = zkr0[cw];
            float2 zb = zkr8[cw];
            float2 v0, v8;
            v0.x = acc[nt][0] + zm2.x + za.x;
            v0.y = acc[nt][1] + zm2.y + za.y;
            v8.x = acc[nt][2] + zm2.x + zb.x;
            v8.y = acc[nt][3] + zm2.y + zb.y;
            o0[cw] = v0;
            o8[cw] = v8;
        }
        __syncthreads();

        // issue stage it+2 into the buffer just consumed
        int t2 = tile + 2 * K3_GRID;
        if (t2 < N_TILES) {
            const char* src = reinterpret_cast<const char*>(g_xbf16) + (size_t)t2 * (TILE_R * 256);
            uint32_t dst = sA + (it & 1) * A_BUF_B;
#pragma unroll
            for (int j = 0; j < 4; j++) {
                int i = t + j * 256;
                int r = i >> 4, c = i & 15;
                CP_ASYNC16(dst + r * 272 + c * 16, src + r * 256 + c * 16);
            }
        }
        CP_COMMIT();
    }
}

// ===========================================================================
extern "C" void kernel_launch(void* const* d_in, const int* in_sizes, int n_in,
                              void* d_out, int out_size) {
    const float* inputs = (const float*)d_in[0];
    const float* Wself  = (const float*)d_in[1];
    const float* Wm     = (const float*)d_in[2];
    const float* Wk     = (const float*)d_in[3];
    float* out = (float*)d_out;
    (void)in_sizes; (void)n_in; (void)out_size;

    const size_t S2 = (size_t)(128 * 129 + 64 * 129) * sizeof(float);
    cudaFuncSetAttribute(k2_bias, cudaFuncAttributeMaxDynamicSharedMemorySize, (int)S2);
    cudaFuncSetAttribute(k3_main, cudaFuncAttributeMaxDynamicSharedMemorySize, K3_SMEM);

    k1_reduce<<<2048, 128>>>(inputs);
    k2_bias<<<128, 128, S2>>>(Wm, Wk);
    k3_main<<<K3_GRID, K3_THREADS, K3_SMEM>>>(Wself, out);
}